// round 5
// baseline (speedup 1.0000x reference)
#include <cuda_runtime.h>
#include <math.h>

#define Nn     8192
#define Bb     4
#define Ee     262144
#define EMBED  64
#define HIDDEN 512
#define OUTD   64
#define DCAP   192
#define TBLK   (DCAP + 1)
#define VBLK   32              // 32 blocks * 16 warps = 512 warps (one per k)
#define HBLK   512             // hist: Bb*Ee/4 threads / 512

// Scratch (allocation-free rule: __device__ globals)
__device__ int   g_outdeg[Bb * Nn];
__device__ __align__(16) int g_cnt[Bb * Nn * 4];
__device__ float g_vec[5 * HIDDEN];              // v0 (deg), v1..v4 (per-perturb-slot)
__device__ float g_table[TBLK * OUTD];           // out row per outdeg for cnt==0 nodes
__device__ int   g_queue[Bb * Nn];
__device__ int   g_qcnt;

// ---------------------------------------------------------------------------
// Fused vec + hist.
// vec blocks [0,VBLK): warp per k.  omega[n,j] = H[n, j/4]  =>
//   w1s[k,e] = sum_{m<4} w1[k, e*4+m];  v0 = w1s.proj_b ; vb = w1s.proj_w[:,b]
// hist blocks [VBLK, VBLK+HBLK): 4 edges/thread, int4 loads, global atomics.
__global__ void vechist_kernel(const int* __restrict__ ei, const int* __restrict__ pert,
                               const float* __restrict__ w1,
                               const float* __restrict__ proj_w,
                               const float* __restrict__ proj_b) {
    if (blockIdx.x < VBLK) {
        int k    = blockIdx.x * 16 + (threadIdx.x >> 5);   // 512 warps -> k
        int lane = threadIdx.x & 31;
        float a0 = 0.f, a1 = 0.f, a2 = 0.f, a3 = 0.f, a4 = 0.f;
        const float* row = w1 + (size_t)k * (4 * EMBED);
        #pragma unroll
        for (int j = 0; j < 2; j++) {
            int e = lane * 2 + j;
            float4 w4 = __ldg((const float4*)(row + e * 4));
            float s = w4.x + w4.y + w4.z + w4.w;
            a0 += s * __ldg(proj_b + e);
            float4 pw = __ldg((const float4*)(proj_w + e * 4));  // (EMBED,B) row-major
            a1 += s * pw.x; a2 += s * pw.y; a3 += s * pw.z; a4 += s * pw.w;
        }
        #pragma unroll
        for (int o = 16; o > 0; o >>= 1) {
            a0 += __shfl_down_sync(0xffffffffu, a0, o);
            a1 += __shfl_down_sync(0xffffffffu, a1, o);
            a2 += __shfl_down_sync(0xffffffffu, a2, o);
            a3 += __shfl_down_sync(0xffffffffu, a3, o);
            a4 += __shfl_down_sync(0xffffffffu, a4, o);
        }
        if (lane == 0) {
            g_vec[k]              = a0;
            g_vec[HIDDEN + k]     = a1;
            g_vec[2 * HIDDEN + k] = a2;
            g_vec[3 * HIDDEN + k] = a3;
            g_vec[4 * HIDDEN + k] = a4;
        }
        return;
    }
    __shared__ int p[4];
    if (threadIdx.x < 4) p[threadIdx.x] = pert[threadIdx.x];
    __syncthreads();
    int idx = (blockIdx.x - VBLK) * blockDim.x + threadIdx.x;  // Bb*Ee/4 threads
    int b  = idx >> 16;                                        // (idx*4) >> 18
    int e4 = (idx & ((Ee / 4) - 1)) * 4;
    const int* base = ei + (size_t)b * 2 * Ee;
    int4 src = __ldg((const int4*)(base + e4));
    int4 dst = __ldg((const int4*)(base + Ee + e4));
    int gb = b * Nn;
    #pragma unroll
    for (int j = 0; j < 4; j++) {
        int s = (j == 0) ? src.x : (j == 1) ? src.y : (j == 2) ? src.z : src.w;
        int d = (j == 0) ? dst.x : (j == 1) ? dst.y : (j == 2) ? dst.z : dst.w;
        atomicAdd(&g_outdeg[gb + s], 1);
        bool h0 = (d == p[0]), h1 = (d == p[1]), h2 = (d == p[2]), h3 = (d == p[3]);
        if (h0 | h1 | h2 | h3) {
            int cb = (gb + s) * 4;
            if (h0) atomicAdd(&g_cnt[cb + 0], 1);
            if (h1) atomicAdd(&g_cnt[cb + 1], 1);
            if (h2) atomicAdd(&g_cnt[cb + 2], 1);
            if (h3) atomicAdd(&g_cnt[cb + 3], 1);
        }
    }
}

// ---------------------------------------------------------------------------
// 512-thread pipeline: h = b1 + deg*v0 + sum cnt*vb ; LN ; exact GELU ; @ w2.T + b2
__device__ __forceinline__ void node_pipeline512(
    float deg, float c0, float c1, float c2, float c3,
    const float* __restrict__ b1, const float* __restrict__ ln_g,
    const float* __restrict__ ln_b, const float* __restrict__ w2,
    const float* __restrict__ b2, float* __restrict__ out) {

    __shared__ float sh[HIDDEN];
    __shared__ float rs[16], rq[16];
    __shared__ float s_mu, s_inv;
    int t = threadIdx.x;

    float h = b1[t] + deg * g_vec[t]
            + c0 * g_vec[HIDDEN + t]     + c1 * g_vec[2 * HIDDEN + t]
            + c2 * g_vec[3 * HIDDEN + t] + c3 * g_vec[4 * HIDDEN + t];

    float ps = h, pq = h * h;
    #pragma unroll
    for (int o = 16; o > 0; o >>= 1) {
        ps += __shfl_down_sync(0xffffffffu, ps, o);
        pq += __shfl_down_sync(0xffffffffu, pq, o);
    }
    if ((t & 31) == 0) { rs[t >> 5] = ps; rq[t >> 5] = pq; }
    __syncthreads();
    if (t < 32) {
        float a = (t < 16) ? rs[t] : 0.f;
        float q = (t < 16) ? rq[t] : 0.f;
        #pragma unroll
        for (int o = 8; o > 0; o >>= 1) {
            a += __shfl_down_sync(0xffffffffu, a, o);
            q += __shfl_down_sync(0xffffffffu, q, o);
        }
        if (t == 0) {
            float mu  = a * (1.f / HIDDEN);
            float var = q * (1.f / HIDDEN) - mu * mu;
            s_mu  = mu;
            s_inv = rsqrtf(var + 1e-5f);
        }
    }
    __syncthreads();

    float x = (h - s_mu) * s_inv * ln_g[t] + ln_b[t];
    sh[t] = 0.5f * x * (1.f + erff(x * 0.7071067811865476f));   // exact GELU
    __syncthreads();

    // GEMV: thread (o=t>>3, part=t&7) sums k = part + 8j  (coalesced w2 sectors)
    int o = t >> 3, part = t & 7;
    const float* w2r = w2 + (size_t)o * HIDDEN + part;
    float acc = 0.f;
    #pragma unroll 16
    for (int j = 0; j < HIDDEN / 8; j++)
        acc += sh[part + 8 * j] * w2r[8 * j];
    #pragma unroll
    for (int off = 4; off > 0; off >>= 1)
        acc += __shfl_down_sync(0xffffffffu, acc, off);
    if (part == 0) out[o] = acc + b2[o];
}

// ---------------------------------------------------------------------------
__global__ void table_kernel(const float* __restrict__ b1, const float* __restrict__ ln_g,
                             const float* __restrict__ ln_b, const float* __restrict__ w2,
                             const float* __restrict__ b2) {
    node_pipeline512((float)blockIdx.x, 0.f, 0.f, 0.f, 0.f,
                     b1, ln_g, ln_b, w2, b2, g_table + (size_t)blockIdx.x * OUTD);
}

// ---------------------------------------------------------------------------
// Warp-per-node fast path; slow nodes queued for fixup.
__global__ void node_kernel(float* __restrict__ out) {
    int bn   = (blockIdx.x * blockDim.x + threadIdx.x) >> 5;   // Bb*Nn warps
    int lane = threadIdx.x & 31;
    int deg = __ldg(&g_outdeg[bn]);
    int4 c  = *(const int4*)(g_cnt + (size_t)bn * 4);
    if (((c.x | c.y | c.z | c.w) == 0) && deg <= DCAP) {
        float2 v = *(const float2*)(g_table + deg * OUTD + lane * 2);
        *(float2*)(out + (size_t)bn * OUTD + lane * 2) = v;
    } else if (lane == 0) {
        int q = atomicAdd(&g_qcnt, 1);
        g_queue[q] = bn;
    }
}

__global__ void fixup_kernel(const float* __restrict__ b1, const float* __restrict__ ln_g,
                             const float* __restrict__ ln_b, const float* __restrict__ w2,
                             const float* __restrict__ b2, float* __restrict__ out) {
    int qn = g_qcnt;
    for (int q = blockIdx.x; q < qn; q += gridDim.x) {
        int bn  = g_queue[q];
        int deg = g_outdeg[bn];
        int4 c  = *(const int4*)(g_cnt + (size_t)bn * 4);
        node_pipeline512((float)deg, (float)c.x, (float)c.y, (float)c.z, (float)c.w,
                         b1, ln_g, ln_b, w2, b2, out + (size_t)bn * OUTD);
        __syncthreads();
    }
}

// ---------------------------------------------------------------------------
extern "C" void kernel_launch(void* const* d_in, const int* in_sizes, int n_in,
                              void* d_out, int out_size) {
    const int*   ei     = (const int*)  d_in[0];
    const int*   pert   = (const int*)  d_in[1];
    const float* proj_w = (const float*)d_in[2];
    const float* proj_b = (const float*)d_in[3];
    const float* w1     = (const float*)d_in[4];
    const float* b1     = (const float*)d_in[5];
    const float* ln_g   = (const float*)d_in[6];
    const float* ln_b   = (const float*)d_in[7];
    const float* w2     = (const float*)d_in[8];
    const float* b2     = (const float*)d_in[9];
    float* out = (float*)d_out;

    // Zero scratch via DMA memset nodes (graph-capturable, no SM time).
    void *p_outdeg, *p_cnt, *p_qcnt;
    cudaGetSymbolAddress(&p_outdeg, g_outdeg);
    cudaGetSymbolAddress(&p_cnt,    g_cnt);
    cudaGetSymbolAddress(&p_qcnt,   g_qcnt);
    cudaMemsetAsync(p_outdeg, 0, sizeof(int) * Bb * Nn);
    cudaMemsetAsync(p_cnt,    0, sizeof(int) * Bb * Nn * 4);
    cudaMemsetAsync(p_qcnt,   0, sizeof(int));

    vechist_kernel<<<VBLK + HBLK, 512>>>(ei, pert, w1, proj_w, proj_b);
    table_kernel<<<TBLK, 512>>>(b1, ln_g, ln_b, w2, b2);
    node_kernel<<<(Bb * Nn * 32) / 256, 256>>>(out);
    fixup_kernel<<<64, 512>>>(b1, ln_g, ln_b, w2, b2, out);
}

// round 6
// speedup vs baseline: 2.4402x; 2.4402x over previous
#include <cuda_runtime.h>
#include <math.h>

#define Nn     8192
#define Bb     4
#define Ee     262144
#define EMBED  64
#define HIDDEN 512
#define OUTD   64
#define DCAP   192
#define TBLK   (DCAP + 1)      // 193 table blocks
#define VBLK   32              // vec: 32 blocks * 16 warps = 512 warps (one per k)
#define HBLK   512             // hist: Bb*Ee/4 threads / 512
#define FBLK   512             // fixup blocks (≈1 node each)

// Scratch (allocation-free rule: __device__ globals)
__device__ int   g_outdeg[Bb * Nn];
__device__ __align__(16) int g_cnt[Bb * Nn * 4];
__device__ int   g_mark[Bb * Nn];
__device__ float g_vec[5 * HIDDEN];              // v0 (deg), v1..v4 (per-perturb-slot)
__device__ float g_table[TBLK * OUTD];           // out row per outdeg for cnt==0 nodes
__device__ int   g_queue[Bb * Nn];
__device__ int   g_qcnt;

// ---------------------------------------------------------------------------
__global__ void zero_kernel() {
    int i = blockIdx.x * blockDim.x + threadIdx.x;   // 768*256 = 196608 threads
    if (i == 0) g_qcnt = 0;
    if (i < Bb * Nn)            { g_outdeg[i] = 0; return; }
    if (i < 5 * Bb * Nn)        { g_cnt[i - Bb * Nn] = 0; return; }
    if (i < 6 * Bb * Nn)        { g_mark[i - 5 * Bb * Nn] = 0; return; }
}

// ---------------------------------------------------------------------------
// Fused vec + hist(+queue).
// vec blocks [0,VBLK): warp per k.  omega[n,j] = H[n, j/4]  =>
//   w1s[k,e] = sum_{m<4} w1[k, e*4+m];  v0 = w1s.proj_b ; vb = w1s.proj_w[:,b]
// hist blocks: 4 edges/thread, int4 loads; perturb-hit srcs get counted AND
// queued (dedup via atomicOr on g_mark).
__global__ void vechist_kernel(const int* __restrict__ ei, const int* __restrict__ pert,
                               const float* __restrict__ w1,
                               const float* __restrict__ proj_w,
                               const float* __restrict__ proj_b) {
    if (blockIdx.x < VBLK) {
        int k    = blockIdx.x * 16 + (threadIdx.x >> 5);   // 512 warps -> k
        int lane = threadIdx.x & 31;
        float a0 = 0.f, a1 = 0.f, a2 = 0.f, a3 = 0.f, a4 = 0.f;
        const float* row = w1 + (size_t)k * (4 * EMBED);
        #pragma unroll
        for (int j = 0; j < 2; j++) {
            int e = lane * 2 + j;
            float4 w4 = __ldg((const float4*)(row + e * 4));
            float s = w4.x + w4.y + w4.z + w4.w;
            a0 += s * __ldg(proj_b + e);
            float4 pw = __ldg((const float4*)(proj_w + e * 4));  // (EMBED,B) row-major
            a1 += s * pw.x; a2 += s * pw.y; a3 += s * pw.z; a4 += s * pw.w;
        }
        #pragma unroll
        for (int o = 16; o > 0; o >>= 1) {
            a0 += __shfl_down_sync(0xffffffffu, a0, o);
            a1 += __shfl_down_sync(0xffffffffu, a1, o);
            a2 += __shfl_down_sync(0xffffffffu, a2, o);
            a3 += __shfl_down_sync(0xffffffffu, a3, o);
            a4 += __shfl_down_sync(0xffffffffu, a4, o);
        }
        if (lane == 0) {
            g_vec[k]              = a0;
            g_vec[HIDDEN + k]     = a1;
            g_vec[2 * HIDDEN + k] = a2;
            g_vec[3 * HIDDEN + k] = a3;
            g_vec[4 * HIDDEN + k] = a4;
        }
        return;
    }
    __shared__ int p[4];
    if (threadIdx.x < 4) p[threadIdx.x] = pert[threadIdx.x];
    __syncthreads();
    int idx = (blockIdx.x - VBLK) * blockDim.x + threadIdx.x;  // Bb*Ee/4 threads
    int b  = idx >> 16;                                        // (idx*4) >> 18
    int e4 = (idx & ((Ee / 4) - 1)) * 4;
    const int* base = ei + (size_t)b * 2 * Ee;
    int4 src = __ldg((const int4*)(base + e4));
    int4 dst = __ldg((const int4*)(base + Ee + e4));
    int gb = b * Nn;
    #pragma unroll
    for (int j = 0; j < 4; j++) {
        int s = (j == 0) ? src.x : (j == 1) ? src.y : (j == 2) ? src.z : src.w;
        int d = (j == 0) ? dst.x : (j == 1) ? dst.y : (j == 2) ? dst.z : dst.w;
        int bn = gb + s;
        atomicAdd(&g_outdeg[bn], 1);
        bool h0 = (d == p[0]), h1 = (d == p[1]), h2 = (d == p[2]), h3 = (d == p[3]);
        if (h0 | h1 | h2 | h3) {
            int cb = bn * 4;
            if (h0) atomicAdd(&g_cnt[cb + 0], 1);
            if (h1) atomicAdd(&g_cnt[cb + 1], 1);
            if (h2) atomicAdd(&g_cnt[cb + 2], 1);
            if (h3) atomicAdd(&g_cnt[cb + 3], 1);
            if (atomicOr(&g_mark[bn], 1) == 0) {
                int q = atomicAdd(&g_qcnt, 1);
                g_queue[q] = bn;
            }
        }
    }
}

// ---------------------------------------------------------------------------
// 512-thread pipeline: h = b1 + deg*v0 + sum cnt*vb ; LN ; exact GELU ; @ w2.T + b2
__device__ __forceinline__ void node_pipeline512(
    float deg, float c0, float c1, float c2, float c3,
    const float* __restrict__ b1, const float* __restrict__ ln_g,
    const float* __restrict__ ln_b, const float* __restrict__ w2,
    const float* __restrict__ b2, float* __restrict__ out) {

    __shared__ float sh[HIDDEN];
    __shared__ float rs[16], rq[16];
    __shared__ float s_mu, s_inv;
    int t = threadIdx.x;

    float h = b1[t] + deg * g_vec[t]
            + c0 * g_vec[HIDDEN + t]     + c1 * g_vec[2 * HIDDEN + t]
            + c2 * g_vec[3 * HIDDEN + t] + c3 * g_vec[4 * HIDDEN + t];

    float ps = h, pq = h * h;
    #pragma unroll
    for (int o = 16; o > 0; o >>= 1) {
        ps += __shfl_down_sync(0xffffffffu, ps, o);
        pq += __shfl_down_sync(0xffffffffu, pq, o);
    }
    if ((t & 31) == 0) { rs[t >> 5] = ps; rq[t >> 5] = pq; }
    __syncthreads();
    if (t < 32) {
        float a = (t < 16) ? rs[t] : 0.f;
        float q = (t < 16) ? rq[t] : 0.f;
        #pragma unroll
        for (int o = 8; o > 0; o >>= 1) {
            a += __shfl_down_sync(0xffffffffu, a, o);
            q += __shfl_down_sync(0xffffffffu, q, o);
        }
        if (t == 0) {
            float mu  = a * (1.f / HIDDEN);
            float var = q * (1.f / HIDDEN) - mu * mu;
            s_mu  = mu;
            s_inv = rsqrtf(var + 1e-5f);
        }
    }
    __syncthreads();

    float x = (h - s_mu) * s_inv * ln_g[t] + ln_b[t];
    sh[t] = 0.5f * x * (1.f + erff(x * 0.7071067811865476f));   // exact GELU
    __syncthreads();

    // GEMV: thread (o=t>>3, part=t&7) sums k = part + 8j
    int o = t >> 3, part = t & 7;
    const float* w2r = w2 + (size_t)o * HIDDEN + part;
    float acc = 0.f;
    #pragma unroll 16
    for (int j = 0; j < HIDDEN / 8; j++)
        acc += sh[part + 8 * j] * w2r[8 * j];
    #pragma unroll
    for (int off = 4; off > 0; off >>= 1)
        acc += __shfl_down_sync(0xffffffffu, acc, off);
    if (part == 0) out[o] = acc + b2[o];
}

// ---------------------------------------------------------------------------
// Fused table + fixup (both depend only on vechist).
// blocks [0,TBLK): table rows; blocks [TBLK, TBLK+FBLK): queued slow nodes.
__global__ void tablefix_kernel(const float* __restrict__ b1, const float* __restrict__ ln_g,
                                const float* __restrict__ ln_b, const float* __restrict__ w2,
                                const float* __restrict__ b2, float* __restrict__ out) {
    if (blockIdx.x < TBLK) {
        node_pipeline512((float)blockIdx.x, 0.f, 0.f, 0.f, 0.f,
                         b1, ln_g, ln_b, w2, b2, g_table + (size_t)blockIdx.x * OUTD);
        return;
    }
    int qn = g_qcnt;
    for (int q = blockIdx.x - TBLK; q < qn; q += FBLK) {
        int bn  = g_queue[q];
        int deg = g_outdeg[bn];
        int4 c  = *(const int4*)(g_cnt + (size_t)bn * 4);
        node_pipeline512((float)deg, (float)c.x, (float)c.y, (float)c.z, (float)c.w,
                         b1, ln_g, ln_b, w2, b2, out + (size_t)bn * OUTD);
        __syncthreads();
    }
}

// ---------------------------------------------------------------------------
// Warp-per-node fast path. Marked nodes are owned by tablefix. The (deg>DCAP,
// unmarked) case is statistically impossible (Poisson(32)) but handled
// correctly by an in-warp pipeline.
__global__ void node_kernel(const float* __restrict__ b1, const float* __restrict__ ln_g,
                            const float* __restrict__ ln_b, const float* __restrict__ w2,
                            const float* __restrict__ b2, float* __restrict__ out) {
    int bn   = (blockIdx.x * blockDim.x + threadIdx.x) >> 5;   // Bb*Nn warps
    int lane = threadIdx.x & 31;
    if (g_mark[bn]) return;                                    // fixup path owns it
    int deg = g_outdeg[bn];
    if (deg <= DCAP) {
        float2 v = *(const float2*)(g_table + deg * OUTD + lane * 2);
        *(float2*)(out + (size_t)bn * OUTD + lane * 2) = v;
        return;
    }
    // --- never-taken safety path: full pipeline within one warp ---
    float dg = (float)deg;
    float hreg[16];
    float ps = 0.f, pq = 0.f;
    #pragma unroll
    for (int i = 0; i < 16; i++) {
        int k = lane + 32 * i;
        float h = b1[k] + dg * g_vec[k];
        hreg[i] = h; ps += h; pq += h * h;
    }
    #pragma unroll
    for (int o = 16; o > 0; o >>= 1) {
        ps += __shfl_xor_sync(0xffffffffu, ps, o);
        pq += __shfl_xor_sync(0xffffffffu, pq, o);
    }
    float mu  = ps * (1.f / HIDDEN);
    float var = pq * (1.f / HIDDEN) - mu * mu;
    float inv = rsqrtf(var + 1e-5f);
    #pragma unroll
    for (int i = 0; i < 16; i++) {
        int k = lane + 32 * i;
        float x = (hreg[i] - mu) * inv * ln_g[k] + ln_b[k];
        hreg[i] = 0.5f * x * (1.f + erff(x * 0.7071067811865476f));
    }
    for (int o = 0; o < OUTD; o++) {
        float acc = 0.f;
        const float* w2r = w2 + (size_t)o * HIDDEN + lane;
        #pragma unroll
        for (int i = 0; i < 16; i++) acc += hreg[i] * w2r[32 * i];
        #pragma unroll
        for (int off = 16; off > 0; off >>= 1)
            acc += __shfl_xor_sync(0xffffffffu, acc, off);
        if (lane == 0) out[(size_t)bn * OUTD + o] = acc + b2[o];
    }
}

// ---------------------------------------------------------------------------
extern "C" void kernel_launch(void* const* d_in, const int* in_sizes, int n_in,
                              void* d_out, int out_size) {
    const int*   ei     = (const int*)  d_in[0];
    const int*   pert   = (const int*)  d_in[1];
    const float* proj_w = (const float*)d_in[2];
    const float* proj_b = (const float*)d_in[3];
    const float* w1     = (const float*)d_in[4];
    const float* b1     = (const float*)d_in[5];
    const float* ln_g   = (const float*)d_in[6];
    const float* ln_b   = (const float*)d_in[7];
    const float* w2     = (const float*)d_in[8];
    const float* b2     = (const float*)d_in[9];
    float* out = (float*)d_out;

    zero_kernel<<<768, 256>>>();
    vechist_kernel<<<VBLK + HBLK, 512>>>(ei, pert, w1, proj_w, proj_b);
    tablefix_kernel<<<TBLK + FBLK, 512>>>(b1, ln_g, ln_b, w2, b2, out);
    node_kernel<<<(Bb * Nn * 32) / 256, 256>>>(b1, ln_g, ln_b, w2, b2, out);
}

// round 7
// speedup vs baseline: 2.8865x; 1.1829x over previous
#include <cuda_runtime.h>
#include <math.h>

#define Nn     8192
#define Bb     4
#define Ee     262144
#define EMBED  64
#define HIDDEN 512
#define OUTD   64
#define DCAP   192
#define TROWS  (DCAP + 1)      // 193 table rows
#define TBLK4  ((TROWS + 3) / 4)   // 49 batched table blocks
#define VBLK   32              // vec: 32 blocks * 16 warps = 512 warps (one per k)
#define HBLK   512             // hist: Bb*Ee/4 threads / 512
#define FBLK4  160             // batched fixup blocks (4 nodes each, 640 capacity/stride)

// Scratch (allocation-free rule: __device__ globals)
__device__ int   g_outdeg[Bb * Nn];
__device__ __align__(16) int g_cnt[Bb * Nn * 4];
__device__ int   g_mark[Bb * Nn];
__device__ float g_vec[5 * HIDDEN];              // v0 (deg), v1..v4 (per-perturb-slot)
__device__ float g_table[TROWS * OUTD];          // out row per outdeg for cnt==0 nodes
__device__ int   g_queue[Bb * Nn];
__device__ int   g_qcnt;

// ---------------------------------------------------------------------------
__global__ void zero_kernel() {
    int i = blockIdx.x * blockDim.x + threadIdx.x;   // 768*256 = 196608 threads
    if (i == 0) g_qcnt = 0;
    if (i < Bb * Nn)            { g_outdeg[i] = 0; return; }
    if (i < 5 * Bb * Nn)        { g_cnt[i - Bb * Nn] = 0; return; }
    if (i < 6 * Bb * Nn)        { g_mark[i - 5 * Bb * Nn] = 0; return; }
}

// ---------------------------------------------------------------------------
// Fused vec + hist(+queue).
__global__ void vechist_kernel(const int* __restrict__ ei, const int* __restrict__ pert,
                               const float* __restrict__ w1,
                               const float* __restrict__ proj_w,
                               const float* __restrict__ proj_b) {
    if (blockIdx.x < VBLK) {
        int k    = blockIdx.x * 16 + (threadIdx.x >> 5);   // 512 warps -> k
        int lane = threadIdx.x & 31;
        float a0 = 0.f, a1 = 0.f, a2 = 0.f, a3 = 0.f, a4 = 0.f;
        const float* row = w1 + (size_t)k * (4 * EMBED);
        #pragma unroll
        for (int j = 0; j < 2; j++) {
            int e = lane * 2 + j;
            float4 w4 = __ldg((const float4*)(row + e * 4));
            float s = w4.x + w4.y + w4.z + w4.w;
            a0 += s * __ldg(proj_b + e);
            float4 pw = __ldg((const float4*)(proj_w + e * 4));  // (EMBED,B) row-major
            a1 += s * pw.x; a2 += s * pw.y; a3 += s * pw.z; a4 += s * pw.w;
        }
        #pragma unroll
        for (int o = 16; o > 0; o >>= 1) {
            a0 += __shfl_down_sync(0xffffffffu, a0, o);
            a1 += __shfl_down_sync(0xffffffffu, a1, o);
            a2 += __shfl_down_sync(0xffffffffu, a2, o);
            a3 += __shfl_down_sync(0xffffffffu, a3, o);
            a4 += __shfl_down_sync(0xffffffffu, a4, o);
        }
        if (lane == 0) {
            g_vec[k]              = a0;
            g_vec[HIDDEN + k]     = a1;
            g_vec[2 * HIDDEN + k] = a2;
            g_vec[3 * HIDDEN + k] = a3;
            g_vec[4 * HIDDEN + k] = a4;
        }
        return;
    }
    __shared__ int p[4];
    if (threadIdx.x < 4) p[threadIdx.x] = pert[threadIdx.x];
    __syncthreads();
    int idx = (blockIdx.x - VBLK) * blockDim.x + threadIdx.x;  // Bb*Ee/4 threads
    int b  = idx >> 16;                                        // (idx*4) >> 18
    int e4 = (idx & ((Ee / 4) - 1)) * 4;
    const int* base = ei + (size_t)b * 2 * Ee;
    int4 src = __ldg((const int4*)(base + e4));
    int4 dst = __ldg((const int4*)(base + Ee + e4));
    int gb = b * Nn;
    #pragma unroll
    for (int j = 0; j < 4; j++) {
        int s = (j == 0) ? src.x : (j == 1) ? src.y : (j == 2) ? src.z : src.w;
        int d = (j == 0) ? dst.x : (j == 1) ? dst.y : (j == 2) ? dst.z : dst.w;
        int bn = gb + s;
        atomicAdd(&g_outdeg[bn], 1);
        bool h0 = (d == p[0]), h1 = (d == p[1]), h2 = (d == p[2]), h3 = (d == p[3]);
        if (h0 | h1 | h2 | h3) {
            int cb = bn * 4;
            if (h0) atomicAdd(&g_cnt[cb + 0], 1);
            if (h1) atomicAdd(&g_cnt[cb + 1], 1);
            if (h2) atomicAdd(&g_cnt[cb + 2], 1);
            if (h3) atomicAdd(&g_cnt[cb + 3], 1);
            if (atomicOr(&g_mark[bn], 1) == 0) {
                int q = atomicAdd(&g_qcnt, 1);
                g_queue[q] = bn;
            }
        }
    }
}

// ---------------------------------------------------------------------------
// Batched 512-thread pipeline: 4 nodes per block. One g_vec/b1/ln/w2 load
// feeds 4 accumulators -> 4x less L2 traffic on the 128KB w2 matrix.
// Duplicate out pointers are allowed (same inputs -> same value, benign race).
__device__ __forceinline__ void node_pipeline4(
    const float* __restrict__ dg, const float (*__restrict__ cc)[4],
    const float* __restrict__ b1, const float* __restrict__ ln_g,
    const float* __restrict__ ln_b, const float* __restrict__ w2,
    const float* __restrict__ b2, float* const* __restrict__ outs) {

    __shared__ float sh[4][HIDDEN];
    __shared__ float rs[4][16], rq[4][16];
    __shared__ float s_mu[4], s_inv[4];
    int t = threadIdx.x;

    float v0 = g_vec[t];
    float v1 = g_vec[HIDDEN + t],     v2 = g_vec[2 * HIDDEN + t];
    float v3 = g_vec[3 * HIDDEN + t], v4 = g_vec[4 * HIDDEN + t];
    float b1t = b1[t];

    float h[4], ps[4], pq[4];
    #pragma unroll
    for (int i = 0; i < 4; i++) {
        h[i] = b1t + dg[i] * v0 + cc[i][0] * v1 + cc[i][1] * v2
                                + cc[i][2] * v3 + cc[i][3] * v4;
        ps[i] = h[i]; pq[i] = h[i] * h[i];
    }
    #pragma unroll
    for (int o = 16; o > 0; o >>= 1) {
        #pragma unroll
        for (int i = 0; i < 4; i++) {
            ps[i] += __shfl_down_sync(0xffffffffu, ps[i], o);
            pq[i] += __shfl_down_sync(0xffffffffu, pq[i], o);
        }
    }
    if ((t & 31) == 0) {
        #pragma unroll
        for (int i = 0; i < 4; i++) { rs[i][t >> 5] = ps[i]; rq[i][t >> 5] = pq[i]; }
    }
    __syncthreads();
    if (t < 32) {
        float a[4], q[4];
        #pragma unroll
        for (int i = 0; i < 4; i++) {
            a[i] = (t < 16) ? rs[i][t] : 0.f;
            q[i] = (t < 16) ? rq[i][t] : 0.f;
        }
        #pragma unroll
        for (int o = 8; o > 0; o >>= 1) {
            #pragma unroll
            for (int i = 0; i < 4; i++) {
                a[i] += __shfl_down_sync(0xffffffffu, a[i], o);
                q[i] += __shfl_down_sync(0xffffffffu, q[i], o);
            }
        }
        if (t == 0) {
            #pragma unroll
            for (int i = 0; i < 4; i++) {
                float mu  = a[i] * (1.f / HIDDEN);
                float var = q[i] * (1.f / HIDDEN) - mu * mu;
                s_mu[i]  = mu;
                s_inv[i] = rsqrtf(var + 1e-5f);
            }
        }
    }
    __syncthreads();

    float g = ln_g[t], bb = ln_b[t];
    #pragma unroll
    for (int i = 0; i < 4; i++) {
        float x = (h[i] - s_mu[i]) * s_inv[i] * g + bb;
        sh[i][t] = 0.5f * x * (1.f + erff(x * 0.7071067811865476f));  // exact GELU
    }
    __syncthreads();

    // GEMV: thread (o=t>>3, part=t&7); each w2 load feeds 4 accumulators.
    int o = t >> 3, part = t & 7;
    const float* w2r = w2 + (size_t)o * HIDDEN + part;
    float acc[4] = {0.f, 0.f, 0.f, 0.f};
    #pragma unroll 16
    for (int j = 0; j < HIDDEN / 8; j++) {
        float w = w2r[8 * j];
        int k = part + 8 * j;
        acc[0] += sh[0][k] * w; acc[1] += sh[1][k] * w;
        acc[2] += sh[2][k] * w; acc[3] += sh[3][k] * w;
    }
    #pragma unroll
    for (int off = 4; off > 0; off >>= 1) {
        #pragma unroll
        for (int i = 0; i < 4; i++)
            acc[i] += __shfl_down_sync(0xffffffffu, acc[i], off);
    }
    if (part == 0) {
        float bo = b2[o];
        #pragma unroll
        for (int i = 0; i < 4; i++) outs[i][o] = acc[i] + bo;
    }
}

// ---------------------------------------------------------------------------
// Fused batched table + fixup (both depend only on vechist).
__global__ void tablefix_kernel(const float* __restrict__ b1, const float* __restrict__ ln_g,
                                const float* __restrict__ ln_b, const float* __restrict__ w2,
                                const float* __restrict__ b2, float* __restrict__ out) {
    float dg[4], cc[4][4];
    float* outs[4];
    if (blockIdx.x < TBLK4) {
        #pragma unroll
        for (int i = 0; i < 4; i++) {
            int r = blockIdx.x * 4 + i;
            if (r > DCAP) r = DCAP;                 // duplicate write, benign
            dg[i] = (float)r;
            cc[i][0] = cc[i][1] = cc[i][2] = cc[i][3] = 0.f;
            outs[i] = g_table + (size_t)r * OUTD;
        }
        node_pipeline4(dg, cc, b1, ln_g, ln_b, w2, b2, outs);
        return;
    }
    int qn = g_qcnt;
    if (qn == 0) return;
    for (int q0 = (blockIdx.x - TBLK4) * 4; q0 < qn; q0 += FBLK4 * 4) {
        #pragma unroll
        for (int i = 0; i < 4; i++) {
            int q = q0 + i; if (q >= qn) q = qn - 1;   // duplicate, benign
            int bn  = g_queue[q];
            dg[i] = (float)g_outdeg[bn];
            int4 c = *(const int4*)(g_cnt + (size_t)bn * 4);
            cc[i][0] = (float)c.x; cc[i][1] = (float)c.y;
            cc[i][2] = (float)c.z; cc[i][3] = (float)c.w;
            outs[i] = out + (size_t)bn * OUTD;
        }
        node_pipeline4(dg, cc, b1, ln_g, ln_b, w2, b2, outs);
        __syncthreads();
    }
}

// ---------------------------------------------------------------------------
// Fast path: 4 nodes per warp, prefetched table-row gathers (MLP=4),
// streaming stores. Marked nodes owned by tablefix. deg>DCAP unmarked is
// statistically impossible but handled by an in-warp pipeline.
__global__ void node_kernel(const float* __restrict__ b1, const float* __restrict__ ln_g,
                            const float* __restrict__ ln_b, const float* __restrict__ w2,
                            const float* __restrict__ b2, float* __restrict__ out) {
    int warp = (blockIdx.x * blockDim.x + threadIdx.x) >> 5;   // 8192 warps
    int lane = threadIdx.x & 31;
    int bn0  = warp * 4;

    int mk = 0, dgl = 0;
    if (lane < 4) { mk = g_mark[bn0 + lane]; dgl = g_outdeg[bn0 + lane]; }

    float2 v[4];
    int deg[4], mark[4];
    #pragma unroll
    for (int i = 0; i < 4; i++) {
        mark[i] = __shfl_sync(0xffffffffu, mk,  i);
        deg[i]  = __shfl_sync(0xffffffffu, dgl, i);
        int d = (deg[i] <= DCAP) ? deg[i] : DCAP;
        v[i] = __ldg((const float2*)(g_table + d * OUTD + lane * 2)); // MLP=4
    }
    #pragma unroll
    for (int i = 0; i < 4; i++) {
        if (mark[i]) continue;                                  // fixup owns it
        if (deg[i] <= DCAP) {
            float2* dst = (float2*)(out + (size_t)(bn0 + i) * OUTD + lane * 2);
            __stcs(dst, v[i]);
            continue;
        }
        // --- never-taken safety path: full pipeline within one warp ---
        float dgf = (float)deg[i];
        float hreg[16];
        float ps = 0.f, pq = 0.f;
        #pragma unroll
        for (int r = 0; r < 16; r++) {
            int k = lane + 32 * r;
            float h = b1[k] + dgf * g_vec[k];
            hreg[r] = h; ps += h; pq += h * h;
        }
        #pragma unroll
        for (int o = 16; o > 0; o >>= 1) {
            ps += __shfl_xor_sync(0xffffffffu, ps, o);
            pq += __shfl_xor_sync(0xffffffffu, pq, o);
        }
        float mu  = ps * (1.f / HIDDEN);
        float var = pq * (1.f / HIDDEN) - mu * mu;
        float inv = rsqrtf(var + 1e-5f);
        #pragma unroll
        for (int r = 0; r < 16; r++) {
            int k = lane + 32 * r;
            float x = (hreg[r] - mu) * inv * ln_g[k] + ln_b[k];
            hreg[r] = 0.5f * x * (1.f + erff(x * 0.7071067811865476f));
        }
        for (int o = 0; o < OUTD; o++) {
            float acc = 0.f;
            const float* w2r = w2 + (size_t)o * HIDDEN + lane;
            #pragma unroll
            for (int r = 0; r < 16; r++) acc += hreg[r] * w2r[32 * r];
            #pragma unroll
            for (int off = 16; off > 0; off >>= 1)
                acc += __shfl_xor_sync(0xffffffffu, acc, off);
            if (lane == 0) out[(size_t)(bn0 + i) * OUTD + o] = acc + b2[o];
        }
    }
}

// ---------------------------------------------------------------------------
extern "C" void kernel_launch(void* const* d_in, const int* in_sizes, int n_in,
                              void* d_out, int out_size) {
    const int*   ei     = (const int*)  d_in[0];
    const int*   pert   = (const int*)  d_in[1];
    const float* proj_w = (const float*)d_in[2];
    const float* proj_b = (const float*)d_in[3];
    const float* w1     = (const float*)d_in[4];
    const float* b1     = (const float*)d_in[5];
    const float* ln_g   = (const float*)d_in[6];
    const float* ln_b   = (const float*)d_in[7];
    const float* w2     = (const float*)d_in[8];
    const float* b2     = (const float*)d_in[9];
    float* out = (float*)d_out;

    zero_kernel<<<768, 256>>>();
    vechist_kernel<<<VBLK + HBLK, 512>>>(ei, pert, w1, proj_w, proj_b);
    tablefix_kernel<<<TBLK4 + FBLK4, 512>>>(b1, ln_g, ln_b, w2, b2, out);
    node_kernel<<<1024, 256>>>(b1, ln_g, ln_b, w2, b2, out);
}

// round 8
// speedup vs baseline: 2.9022x; 1.0054x over previous
#include <cuda_runtime.h>
#include <math.h>

#define Nn     8192
#define Bb     4
#define Ee     262144
#define EMBED  64
#define HIDDEN 512
#define OUTD   64
#define DCAP   192
#define TROWS  (DCAP + 1)          // 193 table rows
#define TBLK8  ((TROWS + 7) / 8)   // 25 batched table blocks (rows clamp at DCAP)
#define VBLK   32                  // vec: 32 blocks * 16 warps = 512 warps (one per k)
#define HBLK   512                 // hist: Bb*Ee/4 threads / 512
#define FBLK8  80                  // batched fixup blocks (8 nodes each; 640/pass)
#define NODEB  256                 // node blocks: 256 * 16 warps * 8 nodes = 32768

// Scratch (allocation-free rule: __device__ globals; zero-initialized at load)
__device__ int   g_outdeg[Bb * Nn];
__device__ __align__(16) int g_cnt[Bb * Nn * 4];
__device__ int   g_mark[Bb * Nn];
__device__ float g_vec[5 * HIDDEN];
__device__ float g_table[TROWS * OUTD];
__device__ int   g_queue[Bb * Nn];
__device__ int   g_qcnt;

// ===========================================================================
// K1: vec (blocks 0..VBLK-1) + scratch cleanup (block VBLK).
// Cleanup resets state dirtied by the PREVIOUS call's marked nodes (queue),
// then zeroes qcnt. Unmarked-node state is reset by node blocks in K3.
__global__ void vecclean_kernel(const float* __restrict__ w1,
                                const float* __restrict__ proj_w,
                                const float* __restrict__ proj_b) {
    if (blockIdx.x == VBLK) {
        int qn = g_qcnt;
        for (int q = threadIdx.x; q < qn; q += blockDim.x) {
            int bn = g_queue[q];
            g_outdeg[bn] = 0;
            g_mark[bn]   = 0;
            *(int4*)(g_cnt + (size_t)bn * 4) = make_int4(0, 0, 0, 0);
        }
        __syncthreads();
        if (threadIdx.x == 0) g_qcnt = 0;
        return;
    }
    int k    = blockIdx.x * 16 + (threadIdx.x >> 5);   // 512 warps -> k
    int lane = threadIdx.x & 31;
    float a0 = 0.f, a1 = 0.f, a2 = 0.f, a3 = 0.f, a4 = 0.f;
    const float* row = w1 + (size_t)k * (4 * EMBED);
    #pragma unroll
    for (int j = 0; j < 2; j++) {
        int e = lane * 2 + j;
        float4 w4 = __ldg((const float4*)(row + e * 4));
        float s = w4.x + w4.y + w4.z + w4.w;            // omega interleave fold
        a0 += s * __ldg(proj_b + e);
        float4 pw = __ldg((const float4*)(proj_w + e * 4));
        a1 += s * pw.x; a2 += s * pw.y; a3 += s * pw.z; a4 += s * pw.w;
    }
    #pragma unroll
    for (int o = 16; o > 0; o >>= 1) {
        a0 += __shfl_down_sync(0xffffffffu, a0, o);
        a1 += __shfl_down_sync(0xffffffffu, a1, o);
        a2 += __shfl_down_sync(0xffffffffu, a2, o);
        a3 += __shfl_down_sync(0xffffffffu, a3, o);
        a4 += __shfl_down_sync(0xffffffffu, a4, o);
    }
    if (lane == 0) {
        g_vec[k]              = a0;
        g_vec[HIDDEN + k]     = a1;
        g_vec[2 * HIDDEN + k] = a2;
        g_vec[3 * HIDDEN + k] = a3;
        g_vec[4 * HIDDEN + k] = a4;
    }
}

// ===========================================================================
// Batched 512-thread pipeline: 8 nodes per block. Inputs broadcast via smem.
__device__ __forceinline__ void pipeline8(
    const float* __restrict__ sdg, const float (*__restrict__ scc)[4],
    float* const* __restrict__ souts,
    const float* __restrict__ b1, const float* __restrict__ ln_g,
    const float* __restrict__ ln_b, const float* __restrict__ w2,
    const float* __restrict__ b2) {

    __shared__ float sh[8][HIDDEN];      // 16 KB
    __shared__ float rs[8][16], rq[8][16];
    __shared__ float smu[8], sinv[8];
    int t = threadIdx.x;

    float v0 = g_vec[t];
    float v1 = g_vec[HIDDEN + t],     v2 = g_vec[2 * HIDDEN + t];
    float v3 = g_vec[3 * HIDDEN + t], v4 = g_vec[4 * HIDDEN + t];
    float b1t = b1[t];

    float ps[8], pq[8];
    #pragma unroll
    for (int i = 0; i < 8; i++) {
        float h = b1t + sdg[i] * v0 + scc[i][0] * v1 + scc[i][1] * v2
                                    + scc[i][2] * v3 + scc[i][3] * v4;
        sh[i][t] = h;
        ps[i] = h; pq[i] = h * h;
    }
    #pragma unroll
    for (int o = 16; o > 0; o >>= 1) {
        #pragma unroll
        for (int i = 0; i < 8; i++) {
            ps[i] += __shfl_down_sync(0xffffffffu, ps[i], o);
            pq[i] += __shfl_down_sync(0xffffffffu, pq[i], o);
        }
    }
    if ((t & 31) == 0) {
        #pragma unroll
        for (int i = 0; i < 8; i++) { rs[i][t >> 5] = ps[i]; rq[i][t >> 5] = pq[i]; }
    }
    __syncthreads();
    if (t < 32) {
        #pragma unroll
        for (int i = 0; i < 8; i++) {
            float a = (t < 16) ? rs[i][t] : 0.f;
            float q = (t < 16) ? rq[i][t] : 0.f;
            #pragma unroll
            for (int o = 8; o > 0; o >>= 1) {
                a += __shfl_down_sync(0xffffffffu, a, o);
                q += __shfl_down_sync(0xffffffffu, q, o);
            }
            if (t == 0) {
                float mu  = a * (1.f / HIDDEN);
                float var = q * (1.f / HIDDEN) - mu * mu;
                smu[i]  = mu;
                sinv[i] = rsqrtf(var + 1e-5f);
            }
        }
    }
    __syncthreads();

    float g = ln_g[t], bb = ln_b[t];
    #pragma unroll
    for (int i = 0; i < 8; i++) {
        float x = (sh[i][t] - smu[i]) * sinv[i] * g + bb;
        sh[i][t] = 0.5f * x * (1.f + erff(x * 0.7071067811865476f));  // exact GELU
    }
    __syncthreads();

    // GEMV: thread (o=t>>3, part=t&7); each w2 load feeds 8 accumulators.
    int o = t >> 3, part = t & 7;
    const float* w2r = w2 + (size_t)o * HIDDEN + part;
    float acc[8] = {0.f, 0.f, 0.f, 0.f, 0.f, 0.f, 0.f, 0.f};
    #pragma unroll 16
    for (int j = 0; j < HIDDEN / 8; j++) {
        float w = w2r[8 * j];
        int k = part + 8 * j;
        #pragma unroll
        for (int i = 0; i < 8; i++) acc[i] += sh[i][k] * w;
    }
    #pragma unroll
    for (int off = 4; off > 0; off >>= 1) {
        #pragma unroll
        for (int i = 0; i < 8; i++)
            acc[i] += __shfl_down_sync(0xffffffffu, acc[i], off);
    }
    if (part == 0) {
        float bo = b2[o];
        #pragma unroll
        for (int i = 0; i < 8; i++) souts[i][o] = acc[i] + bo;
    }
}

// ===========================================================================
// K2: table (blocks [0,TBLK8), needs only g_vec) + hist (blocks [TBLK8, +HBLK)).
__global__ void tablehist_kernel(const int* __restrict__ ei, const int* __restrict__ pert,
                                 const float* __restrict__ b1, const float* __restrict__ ln_g,
                                 const float* __restrict__ ln_b, const float* __restrict__ w2,
                                 const float* __restrict__ b2) {
    if (blockIdx.x < TBLK8) {
        __shared__ float sdg[8];
        __shared__ float scc[8][4];
        __shared__ float* souts[8];
        int t = threadIdx.x;
        if (t < 8) {
            int r = blockIdx.x * 8 + t;
            if (r > DCAP) r = DCAP;                   // duplicate write, benign
            sdg[t] = (float)r;
            scc[t][0] = scc[t][1] = scc[t][2] = scc[t][3] = 0.f;
            souts[t] = g_table + (size_t)r * OUTD;
        }
        __syncthreads();
        pipeline8(sdg, scc, souts, b1, ln_g, ln_b, w2, b2);
        return;
    }
    __shared__ int p[4];
    if (threadIdx.x < 4) p[threadIdx.x] = pert[threadIdx.x];
    __syncthreads();
    int idx = (blockIdx.x - TBLK8) * blockDim.x + threadIdx.x;   // Bb*Ee/4 threads
    int b  = idx >> 16;                                          // (idx*4) >> 18
    int e4 = (idx & ((Ee / 4) - 1)) * 4;
    const int* base = ei + (size_t)b * 2 * Ee;
    int4 src = __ldg((const int4*)(base + e4));
    int4 dst = __ldg((const int4*)(base + Ee + e4));
    int gb = b * Nn;
    #pragma unroll
    for (int j = 0; j < 4; j++) {
        int s = (j == 0) ? src.x : (j == 1) ? src.y : (j == 2) ? src.z : src.w;
        int d = (j == 0) ? dst.x : (j == 1) ? dst.y : (j == 2) ? dst.z : dst.w;
        int bn = gb + s;
        atomicAdd(&g_outdeg[bn], 1);
        bool h0 = (d == p[0]), h1 = (d == p[1]), h2 = (d == p[2]), h3 = (d == p[3]);
        if (h0 | h1 | h2 | h3) {
            int cb = bn * 4;
            if (h0) atomicAdd(&g_cnt[cb + 0], 1);
            if (h1) atomicAdd(&g_cnt[cb + 1], 1);
            if (h2) atomicAdd(&g_cnt[cb + 2], 1);
            if (h3) atomicAdd(&g_cnt[cb + 3], 1);
            if (atomicOr(&g_mark[bn], 1) == 0) {
                int q = atomicAdd(&g_qcnt, 1);
                g_queue[q] = bn;
            }
        }
    }
}

// ===========================================================================
// K3: fixup (blocks [0,FBLK8), queued marked nodes) + node fast path
// (blocks [FBLK8, +NODEB), 8 nodes/warp, MLP=8 table gathers, self-clean
// outdeg of unmarked nodes). Disjoint output rows -> no cross-path races.
__global__ void nodefix_kernel(const float* __restrict__ b1, const float* __restrict__ ln_g,
                               const float* __restrict__ ln_b, const float* __restrict__ w2,
                               const float* __restrict__ b2, float* __restrict__ out) {
    if (blockIdx.x < FBLK8) {
        __shared__ float sdg[8];
        __shared__ float scc[8][4];
        __shared__ float* souts[8];
        int qn = g_qcnt;
        if (qn == 0) return;
        int t = threadIdx.x;
        for (int q0 = blockIdx.x * 8; q0 < qn; q0 += FBLK8 * 8) {
            if (t < 8) {
                int q = q0 + t; if (q >= qn) q = qn - 1;   // in-block duplicate, benign
                int bn = g_queue[q];
                sdg[t] = (float)g_outdeg[bn];
                int4 c = *(const int4*)(g_cnt + (size_t)bn * 4);
                scc[t][0] = (float)c.x; scc[t][1] = (float)c.y;
                scc[t][2] = (float)c.z; scc[t][3] = (float)c.w;
                souts[t] = out + (size_t)bn * OUTD;
            }
            __syncthreads();
            pipeline8(sdg, scc, souts, b1, ln_g, ln_b, w2, b2);
            __syncthreads();
        }
        return;
    }
    int warp = (blockIdx.x - FBLK8) * 16 + (threadIdx.x >> 5);   // 4096 warps
    int lane = threadIdx.x & 31;
    int bn0  = warp * 8;

    int mk = 0, dgl = 0;
    if (lane < 8) { mk = g_mark[bn0 + lane]; dgl = g_outdeg[bn0 + lane]; }

    float2 v[8];
    int deg[8], mark[8];
    #pragma unroll
    for (int i = 0; i < 8; i++) {
        mark[i] = __shfl_sync(0xffffffffu, mk,  i);
        deg[i]  = __shfl_sync(0xffffffffu, dgl, i);
        int d = (deg[i] <= DCAP) ? deg[i] : DCAP;
        v[i] = __ldg((const float2*)(g_table + d * OUTD + lane * 2));  // MLP=8
    }
    // self-clean: unmarked nodes only dirtied outdeg (cnt/mark untouched)
    if (lane < 8 && !mk) g_outdeg[bn0 + lane] = 0;

    #pragma unroll
    for (int i = 0; i < 8; i++) {
        if (mark[i]) continue;                       // fixup path owns it
        if (deg[i] <= DCAP) {
            float2* dst = (float2*)(out + (size_t)(bn0 + i) * OUTD + lane * 2);
            __stcs(dst, v[i]);
            continue;
        }
        // --- never-taken safety path (Poisson(32): P(deg>192)~0): in-warp pipeline
        float dgf = (float)deg[i];
        float hreg[16];
        float ps = 0.f, pq = 0.f;
        #pragma unroll
        for (int r = 0; r < 16; r++) {
            int k = lane + 32 * r;
            float h = b1[k] + dgf * g_vec[k];
            hreg[r] = h; ps += h; pq += h * h;
        }
        #pragma unroll
        for (int o = 16; o > 0; o >>= 1) {
            ps += __shfl_xor_sync(0xffffffffu, ps, o);
            pq += __shfl_xor_sync(0xffffffffu, pq, o);
        }
        float mu  = ps * (1.f / HIDDEN);
        float var = pq * (1.f / HIDDEN) - mu * mu;
        float inv = rsqrtf(var + 1e-5f);
        #pragma unroll
        for (int r = 0; r < 16; r++) {
            int k = lane + 32 * r;
            float x = (hreg[r] - mu) * inv * ln_g[k] + ln_b[k];
            hreg[r] = 0.5f * x * (1.f + erff(x * 0.7071067811865476f));
        }
        for (int o = 0; o < OUTD; o++) {
            float acc = 0.f;
            const float* w2r = w2 + (size_t)o * HIDDEN + lane;
            #pragma unroll
            for (int r = 0; r < 16; r++) acc += hreg[r] * w2r[32 * r];
            #pragma unroll
            for (int off = 16; off > 0; off >>= 1)
                acc += __shfl_xor_sync(0xffffffffu, acc, off);
            if (lane == 0) out[(size_t)(bn0 + i) * OUTD + o] = acc + b2[o];
        }
    }
}

// ===========================================================================
extern "C" void kernel_launch(void* const* d_in, const int* in_sizes, int n_in,
                              void* d_out, int out_size) {
    const int*   ei     = (const int*)  d_in[0];
    const int*   pert   = (const int*)  d_in[1];
    const float* proj_w = (const float*)d_in[2];
    const float* proj_b = (const float*)d_in[3];
    const float* w1     = (const float*)d_in[4];
    const float* b1     = (const float*)d_in[5];
    const float* ln_g   = (const float*)d_in[6];
    const float* ln_b   = (const float*)d_in[7];
    const float* w2     = (const float*)d_in[8];
    const float* b2     = (const float*)d_in[9];
    float* out = (float*)d_out;

    vecclean_kernel<<<VBLK + 1, 512>>>(w1, proj_w, proj_b);
    tablehist_kernel<<<TBLK8 + HBLK, 512>>>(ei, pert, b1, ln_g, ln_b, w2, b2);
    nodefix_kernel<<<FBLK8 + NODEB, 512>>>(b1, ln_g, ln_b, w2, b2, out);
}

// round 9
// speedup vs baseline: 3.0837x; 1.0626x over previous
#include <cuda_runtime.h>
#include <math.h>

#define Nn     8192
#define Bb     4
#define Ee     262144
#define EMBED  64
#define HIDDEN 512
#define OUTD   64
#define DCAP   192
#define TROWS  (DCAP + 1)          // 193 table rows
#define TBLK8  ((TROWS + 7) / 8)   // 25 batched table blocks (rows clamp at DCAP)
#define VBLK   64                  // vec: 64 blocks * 8 k's = 512 k's
#define HBLK   512                 // hist: Bb*Ee/4 threads / 512
#define FBLK8  80                  // batched fixup blocks (8 nodes each; 640/pass)
#define NODEB  256                 // node blocks: 256 * 16 warps * 8 nodes = 32768

// Scratch (allocation-free rule: __device__ globals; zero-initialized at load)
__device__ int   g_outdeg[2][Bb * Nn];           // 2 replicas: halve atomic contention
__device__ __align__(16) int g_cnt[Bb * Nn * 4];
__device__ int   g_mark[Bb * Nn];
__device__ float g_vec[5 * HIDDEN];
__device__ float g_table[TROWS * OUTD];
__device__ int   g_queue[Bb * Nn];
__device__ int   g_qcnt;

// ===========================================================================
// K1: vec (blocks 0..VBLK-1; 8 k's per block, 64 threads per k, one e each)
//     + scratch cleanup (block VBLK): resets state dirtied by the PREVIOUS
//     call's marked nodes, then qcnt. Unmarked outdeg is self-cleaned in K3.
__global__ void vecclean_kernel(const float* __restrict__ w1,
                                const float* __restrict__ proj_w,
                                const float* __restrict__ proj_b) {
    if (blockIdx.x == VBLK) {
        int qn = g_qcnt;
        for (int q = threadIdx.x; q < qn; q += blockDim.x) {
            int bn = g_queue[q];
            g_outdeg[0][bn] = 0;
            g_outdeg[1][bn] = 0;
            g_mark[bn]      = 0;
            *(int4*)(g_cnt + (size_t)bn * 4) = make_int4(0, 0, 0, 0);
        }
        __syncthreads();
        if (threadIdx.x == 0) g_qcnt = 0;
        return;
    }
    int t  = threadIdx.x;
    int kl = t >> 6;                       // k-local 0..7
    int e  = t & 63;
    int k  = blockIdx.x * 8 + kl;
    // omega[n,j] = H[n, j/4]  =>  w1s[k,e] = sum_{m<4} w1[k, e*4+m]
    float4 w4 = __ldg((const float4*)(w1 + (size_t)k * 256 + e * 4));
    float s = w4.x + w4.y + w4.z + w4.w;
    float4 pw = __ldg((const float4*)(proj_w + e * 4));   // (EMBED,B) row-major
    float a0 = s * __ldg(proj_b + e);
    float a1 = s * pw.x, a2 = s * pw.y, a3 = s * pw.z, a4 = s * pw.w;
    #pragma unroll
    for (int o = 16; o > 0; o >>= 1) {
        a0 += __shfl_down_sync(0xffffffffu, a0, o);
        a1 += __shfl_down_sync(0xffffffffu, a1, o);
        a2 += __shfl_down_sync(0xffffffffu, a2, o);
        a3 += __shfl_down_sync(0xffffffffu, a3, o);
        a4 += __shfl_down_sync(0xffffffffu, a4, o);
    }
    __shared__ float pr[16][5];
    if ((t & 31) == 0) {
        int w = t >> 5;
        pr[w][0] = a0; pr[w][1] = a1; pr[w][2] = a2; pr[w][3] = a3; pr[w][4] = a4;
    }
    __syncthreads();
    if (t < 8) {
        int kk = blockIdx.x * 8 + t;
        g_vec[kk]              = pr[t * 2][0] + pr[t * 2 + 1][0];
        g_vec[HIDDEN + kk]     = pr[t * 2][1] + pr[t * 2 + 1][1];
        g_vec[2 * HIDDEN + kk] = pr[t * 2][2] + pr[t * 2 + 1][2];
        g_vec[3 * HIDDEN + kk] = pr[t * 2][3] + pr[t * 2 + 1][3];
        g_vec[4 * HIDDEN + kk] = pr[t * 2][4] + pr[t * 2 + 1][4];
    }
}

// ===========================================================================
// Batched 512-thread pipeline: 8 nodes per block. Inputs broadcast via smem.
__device__ __forceinline__ void pipeline8(
    const float* __restrict__ sdg, const float (*__restrict__ scc)[4],
    float* const* __restrict__ souts,
    const float* __restrict__ b1, const float* __restrict__ ln_g,
    const float* __restrict__ ln_b, const float* __restrict__ w2,
    const float* __restrict__ b2) {

    __shared__ float sh[8][HIDDEN];      // 16 KB
    __shared__ float rs[8][16], rq[8][16];
    __shared__ float smu[8], sinv[8];
    int t = threadIdx.x;

    float v0 = g_vec[t];
    float v1 = g_vec[HIDDEN + t],     v2 = g_vec[2 * HIDDEN + t];
    float v3 = g_vec[3 * HIDDEN + t], v4 = g_vec[4 * HIDDEN + t];
    float b1t = b1[t];

    float ps[8], pq[8];
    #pragma unroll
    for (int i = 0; i < 8; i++) {
        float h = b1t + sdg[i] * v0 + scc[i][0] * v1 + scc[i][1] * v2
                                    + scc[i][2] * v3 + scc[i][3] * v4;
        sh[i][t] = h;
        ps[i] = h; pq[i] = h * h;
    }
    #pragma unroll
    for (int o = 16; o > 0; o >>= 1) {
        #pragma unroll
        for (int i = 0; i < 8; i++) {
            ps[i] += __shfl_down_sync(0xffffffffu, ps[i], o);
            pq[i] += __shfl_down_sync(0xffffffffu, pq[i], o);
        }
    }
    if ((t & 31) == 0) {
        #pragma unroll
        for (int i = 0; i < 8; i++) { rs[i][t >> 5] = ps[i]; rq[i][t >> 5] = pq[i]; }
    }
    __syncthreads();
    if (t < 32) {
        #pragma unroll
        for (int i = 0; i < 8; i++) {
            float a = (t < 16) ? rs[i][t] : 0.f;
            float q = (t < 16) ? rq[i][t] : 0.f;
            #pragma unroll
            for (int o = 8; o > 0; o >>= 1) {
                a += __shfl_down_sync(0xffffffffu, a, o);
                q += __shfl_down_sync(0xffffffffu, q, o);
            }
            if (t == 0) {
                float mu  = a * (1.f / HIDDEN);
                float var = q * (1.f / HIDDEN) - mu * mu;
                smu[i]  = mu;
                sinv[i] = rsqrtf(var + 1e-5f);
            }
        }
    }
    __syncthreads();

    float g = ln_g[t], bb = ln_b[t];
    #pragma unroll
    for (int i = 0; i < 8; i++) {
        float x = (sh[i][t] - smu[i]) * sinv[i] * g + bb;
        sh[i][t] = 0.5f * x * (1.f + erff(x * 0.7071067811865476f));  // exact GELU
    }
    __syncthreads();

    // GEMV: thread (o=t>>3, part=t&7); each w2 load feeds 8 accumulators.
    int o = t >> 3, part = t & 7;
    const float* w2r = w2 + (size_t)o * HIDDEN + part;
    float acc[8] = {0.f, 0.f, 0.f, 0.f, 0.f, 0.f, 0.f, 0.f};
    #pragma unroll 16
    for (int j = 0; j < HIDDEN / 8; j++) {
        float w = w2r[8 * j];
        int k = part + 8 * j;
        #pragma unroll
        for (int i = 0; i < 8; i++) acc[i] += sh[i][k] * w;
    }
    #pragma unroll
    for (int off = 4; off > 0; off >>= 1) {
        #pragma unroll
        for (int i = 0; i < 8; i++)
            acc[i] += __shfl_down_sync(0xffffffffu, acc[i], off);
    }
    if (part == 0) {
        float bo = b2[o];
        #pragma unroll
        for (int i = 0; i < 8; i++) souts[i][o] = acc[i] + bo;
    }
}

// ===========================================================================
// K2: table (blocks [0,TBLK8), needs only g_vec) + hist (blocks [TBLK8, +HBLK)).
__global__ void tablehist_kernel(const int* __restrict__ ei, const int* __restrict__ pert,
                                 const float* __restrict__ b1, const float* __restrict__ ln_g,
                                 const float* __restrict__ ln_b, const float* __restrict__ w2,
                                 const float* __restrict__ b2) {
    if (blockIdx.x < TBLK8) {
        __shared__ float sdg[8];
        __shared__ float scc[8][4];
        __shared__ float* souts[8];
        int t = threadIdx.x;
        if (t < 8) {
            int r = blockIdx.x * 8 + t;
            if (r > DCAP) r = DCAP;                   // duplicate write, benign
            sdg[t] = (float)r;
            scc[t][0] = scc[t][1] = scc[t][2] = scc[t][3] = 0.f;
            souts[t] = g_table + (size_t)r * OUTD;
        }
        __syncthreads();
        pipeline8(sdg, scc, souts, b1, ln_g, ln_b, w2, b2);
        return;
    }
    __shared__ int p[4];
    if (threadIdx.x < 4) p[threadIdx.x] = pert[threadIdx.x];
    __syncthreads();
    int rep = blockIdx.x & 1;                                    // outdeg replica
    int idx = (blockIdx.x - TBLK8) * blockDim.x + threadIdx.x;   // Bb*Ee/4 threads
    int b  = idx >> 16;                                          // (idx*4) >> 18
    int e4 = (idx & ((Ee / 4) - 1)) * 4;
    const int* base = ei + (size_t)b * 2 * Ee;
    int4 src = __ldg((const int4*)(base + e4));
    int4 dst = __ldg((const int4*)(base + Ee + e4));
    int gb = b * Nn;
    #pragma unroll
    for (int j = 0; j < 4; j++) {
        int s = (j == 0) ? src.x : (j == 1) ? src.y : (j == 2) ? src.z : src.w;
        int d = (j == 0) ? dst.x : (j == 1) ? dst.y : (j == 2) ? dst.z : dst.w;
        int bn = gb + s;
        atomicAdd(&g_outdeg[rep][bn], 1);
        bool h0 = (d == p[0]), h1 = (d == p[1]), h2 = (d == p[2]), h3 = (d == p[3]);
        if (h0 | h1 | h2 | h3) {
            int cb = bn * 4;
            if (h0) atomicAdd(&g_cnt[cb + 0], 1);
            if (h1) atomicAdd(&g_cnt[cb + 1], 1);
            if (h2) atomicAdd(&g_cnt[cb + 2], 1);
            if (h3) atomicAdd(&g_cnt[cb + 3], 1);
            if (atomicOr(&g_mark[bn], 1) == 0) {
                int q = atomicAdd(&g_qcnt, 1);
                g_queue[q] = bn;
            }
        }
    }
}

// ===========================================================================
// K3: fixup (blocks [0,FBLK8), queued marked nodes) + node fast path
// (blocks [FBLK8, +NODEB), 8 nodes/warp, MLP=8 table gathers, self-clean
// outdeg replicas of unmarked nodes). Disjoint output rows -> no races.
__global__ void nodefix_kernel(const float* __restrict__ b1, const float* __restrict__ ln_g,
                               const float* __restrict__ ln_b, const float* __restrict__ w2,
                               const float* __restrict__ b2, float* __restrict__ out) {
    if (blockIdx.x < FBLK8) {
        __shared__ float sdg[8];
        __shared__ float scc[8][4];
        __shared__ float* souts[8];
        int qn = g_qcnt;
        if (qn == 0) return;
        int t = threadIdx.x;
        for (int q0 = blockIdx.x * 8; q0 < qn; q0 += FBLK8 * 8) {
            if (t < 8) {
                int q = q0 + t; if (q >= qn) q = qn - 1;   // in-block duplicate, benign
                int bn = g_queue[q];
                sdg[t] = (float)(g_outdeg[0][bn] + g_outdeg[1][bn]);
                int4 c = *(const int4*)(g_cnt + (size_t)bn * 4);
                scc[t][0] = (float)c.x; scc[t][1] = (float)c.y;
                scc[t][2] = (float)c.z; scc[t][3] = (float)c.w;
                souts[t] = out + (size_t)bn * OUTD;
            }
            __syncthreads();
            pipeline8(sdg, scc, souts, b1, ln_g, ln_b, w2, b2);
            __syncthreads();
        }
        return;
    }
    int warp = (blockIdx.x - FBLK8) * 16 + (threadIdx.x >> 5);   // 4096 warps
    int lane = threadIdx.x & 31;
    int bn0  = warp * 8;

    int mk = 0, dgl = 0;
    if (lane < 8) {
        mk  = g_mark[bn0 + lane];
        dgl = g_outdeg[0][bn0 + lane] + g_outdeg[1][bn0 + lane];
    }

    float2 v[8];
    int deg[8], mark[8];
    #pragma unroll
    for (int i = 0; i < 8; i++) {
        mark[i] = __shfl_sync(0xffffffffu, mk,  i);
        deg[i]  = __shfl_sync(0xffffffffu, dgl, i);
        int d = (deg[i] <= DCAP) ? deg[i] : DCAP;
        v[i] = __ldg((const float2*)(g_table + d * OUTD + lane * 2));  // MLP=8
    }
    // self-clean: unmarked nodes only dirtied outdeg (cnt/mark untouched)
    if (lane < 8 && !mk) { g_outdeg[0][bn0 + lane] = 0; g_outdeg[1][bn0 + lane] = 0; }

    #pragma unroll
    for (int i = 0; i < 8; i++) {
        if (mark[i]) continue;                       // fixup path owns it
        if (deg[i] <= DCAP) {
            float2* dst = (float2*)(out + (size_t)(bn0 + i) * OUTD + lane * 2);
            __stcs(dst, v[i]);
            continue;
        }
        // --- never-taken safety path (Poisson(32): P(deg>192)~0): in-warp pipeline
        float dgf = (float)deg[i];
        float hreg[16];
        float ps = 0.f, pq = 0.f;
        #pragma unroll
        for (int r = 0; r < 16; r++) {
            int k = lane + 32 * r;
            float h = b1[k] + dgf * g_vec[k];
            hreg[r] = h; ps += h; pq += h * h;
        }
        #pragma unroll
        for (int o = 16; o > 0; o >>= 1) {
            ps += __shfl_xor_sync(0xffffffffu, ps, o);
            pq += __shfl_xor_sync(0xffffffffu, pq, o);
        }
        float mu  = ps * (1.f / HIDDEN);
        float var = pq * (1.f / HIDDEN) - mu * mu;
        float inv = rsqrtf(var + 1e-5f);
        #pragma unroll
        for (int r = 0; r < 16; r++) {
            int k = lane + 32 * r;
            float x = (hreg[r] - mu) * inv * ln_g[k] + ln_b[k];
            hreg[r] = 0.5f * x * (1.f + erff(x * 0.7071067811865476f));
        }
        for (int o = 0; o < OUTD; o++) {
            float acc = 0.f;
            const float* w2r = w2 + (size_t)o * HIDDEN + lane;
            #pragma unroll
            for (int r = 0; r < 16; r++) acc += hreg[r] * w2r[32 * r];
            #pragma unroll
            for (int off = 16; off > 0; off >>= 1)
                acc += __shfl_xor_sync(0xffffffffu, acc, off);
            if (lane == 0) out[(size_t)(bn0 + i) * OUTD + o] = acc + b2[o];
        }
    }
}

// ===========================================================================
extern "C" void kernel_launch(void* const* d_in, const int* in_sizes, int n_in,
                              void* d_out, int out_size) {
    const int*   ei     = (const int*)  d_in[0];
    const int*   pert   = (const int*)  d_in[1];
    const float* proj_w = (const float*)d_in[2];
    const float* proj_b = (const float*)d_in[3];
    const float* w1     = (const float*)d_in[4];
    const float* b1     = (const float*)d_in[5];
    const float* ln_g   = (const float*)d_in[6];
    const float* ln_b   = (const float*)d_in[7];
    const float* w2     = (const float*)d_in[8];
    const float* b2     = (const float*)d_in[9];
    float* out = (float*)d_out;

    vecclean_kernel<<<VBLK + 1, 512>>>(w1, proj_w, proj_b);
    tablehist_kernel<<<TBLK8 + HBLK, 512>>>(ei, pert, b1, ln_g, ln_b, w2, b2);
    nodefix_kernel<<<FBLK8 + NODEB, 512>>>(b1, ln_g, ln_b, w2, b2, out);
}